// round 1
// baseline (speedup 1.0000x reference)
#include <cuda_runtime.h>
#include <cstddef>

#define N_USERS 50000
#define N_PRODS 50000
#define NN      100000
#define NE      600000
#define HDIM    128
#define ODIM    16

// Scratch (allocation-free rule: __device__ globals)
__device__ float g_x[(size_t)NN * HDIM];    // layer input / conv output
__device__ float g_y[(size_t)NN * HDIM];    // x @ W
__device__ float g_dinv[NN];                // rsqrt(deg)  (also used as deg accumulator)
__device__ int   g_src[NE];
__device__ int   g_dst[NE];
__device__ int   g_is64;

// ---------------------------------------------------------------------------
// Edge dtype detection + conversion (int64 vs int32 canonicalization)
// ---------------------------------------------------------------------------
__global__ void k_detect(const void* __restrict__ edges) {
    if (threadIdx.x == 0 && blockIdx.x == 0) {
        const unsigned int* w = (const unsigned int*)edges;
        int is64 = 1;
        for (int i = 0; i < 64; i++) {
            if (w[2 * i + 1] != 0u) { is64 = 0; break; }
        }
        g_is64 = is64;
    }
}

__global__ void k_convert(const void* __restrict__ edges) {
    int i = blockIdx.x * blockDim.x + threadIdx.x;
    if (i >= NE) return;
    int s, d;
    if (g_is64) {
        const long long* e = (const long long*)edges;
        s = (int)e[i]; d = (int)e[NE + i];
    } else {
        const int* e = (const int*)edges;
        s = e[i]; d = e[NE + i];
    }
    g_src[i] = s;
    g_dst[i] = d;
}

// ---------------------------------------------------------------------------
// Degree / normalization (deg = #in-edges + 1 self loop; dinv = rsqrt(deg))
// ---------------------------------------------------------------------------
__global__ void k_deg_init() {
    int i = blockIdx.x * blockDim.x + threadIdx.x;
    if (i < NN) g_dinv[i] = 1.0f;   // self loop
}

__global__ void k_deg_count() {
    int e = blockIdx.x * blockDim.x + threadIdx.x;
    if (e < NE) atomicAdd(&g_dinv[g_dst[e]], 1.0f);
}

__global__ void k_dinv() {
    int i = blockIdx.x * blockDim.x + threadIdx.x;
    if (i < NN) g_dinv[i] = rsqrtf(g_dinv[i]);
}

// ---------------------------------------------------------------------------
// SGEMM: C[M,128] = (relu?)(A[M,K]) @ W[K,128] (+ bias)
// BM=64, BN=128, BK=32; 256 threads; thread tile 4x8 (cols tx*4 and 64+tx*4)
// ---------------------------------------------------------------------------
__global__ __launch_bounds__(256) void k_gemm(
    const float* __restrict__ A, const float* __restrict__ W,
    const float* __restrict__ bias, float* __restrict__ C,
    int M, int K, int relu_in)
{
    __shared__ float sA[32][68];     // [k][m], padded; rows 272B (16B-aligned)
    __shared__ float sB[32][HDIM];   // [k][n]

    const int tid = threadIdx.x;
    const int tx = tid & 15;         // col tile -> cols tx*4.. and 64+tx*4..
    const int ty = tid >> 4;         // row tile -> rows ty*4..ty*4+3
    const int m0 = blockIdx.x * 64;

    float acc[4][8];
#pragma unroll
    for (int i = 0; i < 4; i++)
#pragma unroll
        for (int j = 0; j < 8; j++) acc[i][j] = 0.f;

    for (int k0 = 0; k0 < K; k0 += 32) {
        // Load A tile (64 x 32) transposed into sA[k][m]
#pragma unroll
        for (int it = 0; it < 2; it++) {
            int idx = tid + it * 256;          // 0..511
            int r  = idx >> 3;                 // 0..63
            int kq = (idx & 7) * 4;            // 0,4,..,28
            int gm = m0 + r;
#pragma unroll
            for (int j = 0; j < 4; j++) {
                int gk = k0 + kq + j;
                float v = 0.f;
                if (gm < M && gk < K) v = A[(size_t)gm * K + gk];
                if (relu_in) v = fmaxf(v, 0.f);
                sA[kq + j][r] = v;
            }
        }
        // Load W tile (32 x 128)
#pragma unroll
        for (int it = 0; it < 4; it++) {
            int idx = tid + it * 256;          // float4 index 0..1023
            int kr = idx >> 5;                 // 0..31
            int c4 = (idx & 31) * 4;
            int gk = k0 + kr;
            float4 v = make_float4(0.f, 0.f, 0.f, 0.f);
            if (gk < K) v = *(const float4*)&W[(size_t)gk * HDIM + c4];
            *(float4*)&sB[kr][c4] = v;
        }
        __syncthreads();

#pragma unroll
        for (int kk = 0; kk < 32; kk++) {
            float4 a  = *(const float4*)&sA[kk][ty * 4];
            float4 b0 = *(const float4*)&sB[kk][tx * 4];
            float4 b1 = *(const float4*)&sB[kk][64 + tx * 4];
            float av[4] = {a.x, a.y, a.z, a.w};
            float bv[8] = {b0.x, b0.y, b0.z, b0.w, b1.x, b1.y, b1.z, b1.w};
#pragma unroll
            for (int i = 0; i < 4; i++)
#pragma unroll
                for (int j = 0; j < 8; j++)
                    acc[i][j] += av[i] * bv[j];
        }
        __syncthreads();
    }

#pragma unroll
    for (int i = 0; i < 4; i++) {
        int gm = m0 + ty * 4 + i;
        if (gm < M) {
            float4 o0, o1;
            o0.x = acc[i][0]; o0.y = acc[i][1]; o0.z = acc[i][2]; o0.w = acc[i][3];
            o1.x = acc[i][4]; o1.y = acc[i][5]; o1.z = acc[i][6]; o1.w = acc[i][7];
            if (bias) {
                o0.x += bias[tx * 4 + 0]; o0.y += bias[tx * 4 + 1];
                o0.z += bias[tx * 4 + 2]; o0.w += bias[tx * 4 + 3];
                o1.x += bias[64 + tx * 4 + 0]; o1.y += bias[64 + tx * 4 + 1];
                o1.z += bias[64 + tx * 4 + 2]; o1.w += bias[64 + tx * 4 + 3];
            }
            *(float4*)&C[(size_t)gm * HDIM + tx * 4] = o0;
            *(float4*)&C[(size_t)gm * HDIM + 64 + tx * 4] = o1;
        }
    }
}

// ---------------------------------------------------------------------------
// out init: g_x = g_y * dinv^2 (self loop) + bias   (float4 granularity)
// ---------------------------------------------------------------------------
__global__ __launch_bounds__(256) void k_init_out(const float* __restrict__ b) {
    int idx = blockIdx.x * blockDim.x + threadIdx.x;   // float4 index
    if (idx < NN * HDIM / 4) {
        int base = idx * 4;
        int i  = base >> 7;           // /128
        int h4 = base & 127;
        float s = g_dinv[i]; s = s * s;
        float4 y = *(const float4*)&g_y[base];
        float4 o;
        o.x = y.x * s + b[h4 + 0];
        o.y = y.y * s + b[h4 + 1];
        o.z = y.z * s + b[h4 + 2];
        o.w = y.w * s + b[h4 + 3];
        *(float4*)&g_x[base] = o;
    }
}

// ---------------------------------------------------------------------------
// Edge scatter: one warp per edge; lane handles one float4 of the 128-wide row
// g_x[dst] += g_y[src] * dinv[src]*dinv[dst]   via red.global.add.v4.f32
// ---------------------------------------------------------------------------
__global__ __launch_bounds__(256) void k_scatter() {
    int gtid = blockIdx.x * blockDim.x + threadIdx.x;
    int wid  = gtid >> 5;
    int lane = gtid & 31;
    if (wid >= NE) return;
    int s = g_src[wid];
    int d = g_dst[wid];
    float norm = g_dinv[s] * g_dinv[d];
    float4 v = *(const float4*)&g_y[(size_t)s * HDIM + lane * 4];
    v.x *= norm; v.y *= norm; v.z *= norm; v.w *= norm;
    float* p = &g_x[(size_t)d * HDIM + lane * 4];
    asm volatile("red.global.add.v4.f32 [%0], {%1,%2,%3,%4};"
                 :: "l"(p), "f"(v.x), "f"(v.y), "f"(v.z), "f"(v.w)
                 : "memory");
}

// ---------------------------------------------------------------------------
// Output GEMM: out[NN,16] = relu(g_x) @ Wo + bo
// ---------------------------------------------------------------------------
__global__ __launch_bounds__(256) void k_out(
    const float* __restrict__ Wo, const float* __restrict__ bo,
    float* __restrict__ out)
{
    __shared__ float sX[64][HDIM];   // 32 KB
    __shared__ float sW[HDIM][ODIM]; //  8 KB
    const int tid = threadIdx.x;
    const int m0 = blockIdx.x * 64;

    // load relu(x) tile
#pragma unroll
    for (int it = 0; it < 8; it++) {
        int idx = tid + it * 256;            // float4 index, 0..2047
        int r  = idx >> 5;
        int c4 = (idx & 31) * 4;
        int gm = m0 + r;
        float4 v = make_float4(0.f, 0.f, 0.f, 0.f);
        if (gm < NN) v = *(const float4*)&g_x[(size_t)gm * HDIM + c4];
        v.x = fmaxf(v.x, 0.f); v.y = fmaxf(v.y, 0.f);
        v.z = fmaxf(v.z, 0.f); v.w = fmaxf(v.w, 0.f);
        *(float4*)&sX[r][c4] = v;
    }
    // load Wo (128x16)
#pragma unroll
    for (int it = 0; it < 8; it++) {
        int idx = tid + it * 256;
        ((float*)sW)[idx] = Wo[idx];
    }
    __syncthreads();

    const int col = tid & 15;
    const int r0  = (tid >> 4) * 4;
    float acc[4] = {0.f, 0.f, 0.f, 0.f};
#pragma unroll 4
    for (int k = 0; k < HDIM; k++) {
        float w = sW[k][col];
        acc[0] += sX[r0 + 0][k] * w;
        acc[1] += sX[r0 + 1][k] * w;
        acc[2] += sX[r0 + 2][k] * w;
        acc[3] += sX[r0 + 3][k] * w;
    }
    float bb = bo[col];
#pragma unroll
    for (int i = 0; i < 4; i++) {
        int gm = m0 + r0 + i;
        if (gm < NN) out[(size_t)gm * ODIM + col] = acc[i] + bb;
    }
}

// ---------------------------------------------------------------------------
extern "C" void kernel_launch(void* const* d_in, const int* in_sizes, int n_in,
                              void* d_out, int out_size) {
    const float* user = (const float*)d_in[0];
    const float* prod = (const float*)d_in[1];
    const void*  edges = d_in[2];
    const float* Wu = (const float*)d_in[3];
    const float* bu = (const float*)d_in[4];
    const float* Wp = (const float*)d_in[5];
    const float* bp = (const float*)d_in[6];
    const float* W1 = (const float*)d_in[7];
    const float* b1 = (const float*)d_in[8];
    const float* W2 = (const float*)d_in[9];
    const float* b2 = (const float*)d_in[10];
    const float* W3 = (const float*)d_in[11];
    const float* b3 = (const float*)d_in[12];
    const float* Wo = (const float*)d_in[13];
    const float* bo = (const float*)d_in[14];
    float* out = (float*)d_out;

    float *px = nullptr, *py = nullptr;
    cudaGetSymbolAddress((void**)&px, g_x);
    cudaGetSymbolAddress((void**)&py, g_y);

    k_detect<<<1, 32>>>(edges);
    k_convert<<<(NE + 255) / 256, 256>>>(edges);
    k_deg_init<<<(NN + 255) / 256, 256>>>();
    k_deg_count<<<(NE + 255) / 256, 256>>>();
    k_dinv<<<(NN + 255) / 256, 256>>>();

    // Input transforms -> g_x
    k_gemm<<<(N_USERS + 63) / 64, 256>>>(user, Wu, bu, px, N_USERS, 64, 0);
    k_gemm<<<(N_PRODS + 63) / 64, 256>>>(prod, Wp, bp, px + (size_t)N_USERS * HDIM,
                                         N_PRODS, 100, 0);

    const float* Ws[3] = {W1, W2, W3};
    const float* bs[3] = {b1, b2, b3};
    for (int l = 0; l < 3; l++) {
        // y = (relu?)(x) @ W   (relu applies to layers 2,3 inputs)
        k_gemm<<<(NN + 63) / 64, 256>>>(px, Ws[l], nullptr, py, NN, HDIM, l > 0 ? 1 : 0);
        // x = y*dinv^2 + b (self loop + bias)
        k_init_out<<<(NN * HDIM / 4 + 255) / 256, 256>>>(bs[l]);
        // x[dst] += y[src]*norm over edges
        k_scatter<<<(NE * 32 + 255) / 256, 256>>>();
    }
    // out = relu(x) @ Wo + bo
    k_out<<<(NN + 63) / 64, 256>>>(Wo, bo, out);
}

// round 3
// speedup vs baseline: 1.0006x; 1.0006x over previous
#include <cuda_runtime.h>
#include <cstdint>
#include <cstddef>

#define N_USERS 50000
#define N_PRODS 50000
#define NN      100000
#define NE      600000
#define HDIM    128
#define ODIM    16

// Scratch (__device__ globals: allocation-free rule)
__device__ float g_x[(size_t)NN * HDIM];
__device__ float g_y[(size_t)NN * HDIM];
__device__ float g_dinv[NN];
__device__ int   g_src[NE];
__device__ int   g_dst[NE];
__device__ int   g_is64;

// ---------------------------------------------------------------------------
// Edge prep
// ---------------------------------------------------------------------------
__global__ void k_detect(const void* __restrict__ edges) {
    if (threadIdx.x == 0 && blockIdx.x == 0) {
        const unsigned int* w = (const unsigned int*)edges;
        int is64 = 1;
        for (int i = 0; i < 64; i++)
            if (w[2 * i + 1] != 0u) { is64 = 0; break; }
        g_is64 = is64;
    }
}
__global__ void k_convert(const void* __restrict__ edges) {
    int i = blockIdx.x * blockDim.x + threadIdx.x;
    if (i >= NE) return;
    int s, d;
    if (g_is64) {
        const long long* e = (const long long*)edges;
        s = (int)e[i]; d = (int)e[NE + i];
    } else {
        const int* e = (const int*)edges;
        s = e[i]; d = e[NE + i];
    }
    g_src[i] = s; g_dst[i] = d;
}
__global__ void k_deg_init() {
    int i = blockIdx.x * blockDim.x + threadIdx.x;
    if (i < NN) g_dinv[i] = 1.0f;
}
__global__ void k_deg_count() {
    int e = blockIdx.x * blockDim.x + threadIdx.x;
    if (e < NE) atomicAdd(&g_dinv[g_dst[e]], 1.0f);
}
__global__ void k_dinv() {
    int i = blockIdx.x * blockDim.x + threadIdx.x;
    if (i < NN) g_dinv[i] = rsqrtf(g_dinv[i]);
}

// ---------------------------------------------------------------------------
// tf32 mma.sync GEMM (sm_80-class PTX; no 103a-only features)
//   C[128-tile, 128] = (relu?)(A[:, 0:Kdim]) @ W[Kdim, 128]
// Fragment-major SMEM staging so mainloop does pure LDS.128 / LDS.64.
// m16n8k8 tf32 fragment maps:
//   A(r,c): lane=(r&7)*4+(c&3), reg=2*((c>>2)&1)+((r>>3)&1)
//   B(k,n): lane=(n&7)*4+(k&3), reg=(k>>2)&1
//   C(row g|g+8, col 2*tg|2*tg+1)
// Epilogue: layer_mode=1 -> g_y=y; x_out=y*dinv^2+bias. layer_mode=0 -> x_out=y+bias.
// ---------------------------------------------------------------------------
__device__ __forceinline__ uint32_t f2tf32(float f) {
    uint32_t u;
    asm("cvt.rna.tf32.f32 %0, %1;" : "=r"(u) : "f"(f));
    return u;
}
__device__ __forceinline__ void mma_tf32(float* c, const uint32_t* a, const uint32_t* b) {
    asm volatile(
        "mma.sync.aligned.m16n8k8.row.col.f32.tf32.tf32.f32 "
        "{%0,%1,%2,%3}, {%4,%5,%6,%7}, {%8,%9}, {%0,%1,%2,%3};"
        : "+f"(c[0]), "+f"(c[1]), "+f"(c[2]), "+f"(c[3])
        : "r"(a[0]), "r"(a[1]), "r"(a[2]), "r"(a[3]), "r"(b[0]), "r"(b[1]));
}

__global__ __launch_bounds__(256) void k_gemm_mma(
    const float* __restrict__ A, int lda, int M, int Kdim,
    const float* __restrict__ W, const float* __restrict__ bias,
    float* __restrict__ y_out, float* __restrict__ x_out,
    int relu_in, int layer_mode)
{
    extern __shared__ uint32_t smf[];
    const int tid = threadIdx.x;
    const int wid = tid >> 5;
    const int lane = tid & 31;
    const int m0 = blockIdx.x * 128;

    const int Kpad = (Kdim + 7) & ~7;
    const int k8cnt = Kpad >> 3;
    uint32_t* Af = smf;                          // k8cnt * 8 tiles * 128 words
    uint32_t* Bf = smf + (size_t)k8cnt * 1024;   // k8cnt * 16 tiles * 64 words

    // ---- stage A (rows m0..m0+127, cols 0..Kpad-1, tf32, relu?) ----
    if (Kpad == 128) {
        // float4 path
        for (int idx4 = tid; idx4 < 128 * 32; idx4 += 256) {
            int r = idx4 >> 5, c4 = (idx4 & 31) << 2;
            int gm = m0 + r;
            float4 v = make_float4(0.f, 0.f, 0.f, 0.f);
            if (gm < M) v = *(const float4*)&A[(size_t)gm * lda + c4];
            if (relu_in) {
                v.x = fmaxf(v.x, 0.f); v.y = fmaxf(v.y, 0.f);
                v.z = fmaxf(v.z, 0.f); v.w = fmaxf(v.w, 0.f);
            }
            uint32_t base = (uint32_t)(((c4 >> 3) * 8 + (r >> 4)) * 128
                          + ((r & 7) * 4) * 4 + (((c4 >> 2) & 1) * 2 + ((r >> 3) & 1)));
            // c = c4+j -> lane advances by j (stride 4 words), reg slot fixed
            Af[base + 0 * 4] = f2tf32(v.x);
            Af[base + 1 * 4] = f2tf32(v.y);
            Af[base + 2 * 4] = f2tf32(v.z);
            Af[base + 3 * 4] = f2tf32(v.w);
        }
    } else {
        for (int idx = tid; idx < 128 * Kpad; idx += 256) {
            int r = idx / Kpad, c = idx - r * Kpad;
            int gm = m0 + r;
            float v = 0.f;
            if (gm < M && c < Kdim) v = A[(size_t)gm * lda + c];
            if (relu_in) v = fmaxf(v, 0.f);
            uint32_t off = (uint32_t)(((c >> 3) * 8 + (r >> 4)) * 128
                         + ((r & 7) * 4 + (c & 3)) * 4
                         + ((c >> 2) & 1) * 2 + ((r >> 3) & 1));
            Af[off] = f2tf32(v);
        }
    }
    // ---- stage B = W (Kdim x 128), tf32 ----
    for (int idx = tid; idx < Kpad * 128; idx += 256) {
        int k = idx >> 7, n = idx & 127;
        float v = (k < Kdim) ? W[(size_t)k * HDIM + n] : 0.f;
        uint32_t off = (uint32_t)(((k >> 3) * 16 + (n >> 3)) * 64
                     + ((n & 7) * 4 + (k & 3)) * 2 + ((k >> 2) & 1));
        Bf[off] = f2tf32(v);
    }
    __syncthreads();

    // ---- mainloop ----
    const int wm = wid & 1;    // 2 m-blocks of 64
    const int wn = wid >> 1;   // 4 n-blocks of 32
    float acc[4][4][4];
#pragma unroll
    for (int mt = 0; mt < 4; mt++)
#pragma unroll
        for (int nt = 0; nt < 4; nt++)
#pragma unroll
            for (int j = 0; j < 4; j++) acc[mt][nt][j] = 0.f;

    const uint32_t* Aw = Af + (wm * 4) * 128 + lane * 4;
    const uint32_t* Bw = Bf + (wn * 4) * 64 + lane * 2;

#pragma unroll 4
    for (int k8 = 0; k8 < k8cnt; k8++) {
        uint32_t a[4][4], b[4][2];
#pragma unroll
        for (int mt = 0; mt < 4; mt++) {
            uint4 t = *(const uint4*)(Aw + (k8 * 8 + mt) * 128);
            a[mt][0] = t.x; a[mt][1] = t.y; a[mt][2] = t.z; a[mt][3] = t.w;
        }
#pragma unroll
        for (int nt = 0; nt < 4; nt++) {
            uint2 t = *(const uint2*)(Bw + (k8 * 16 + nt) * 64);
            b[nt][0] = t.x; b[nt][1] = t.y;
        }
#pragma unroll
        for (int mt = 0; mt < 4; mt++)
#pragma unroll
            for (int nt = 0; nt < 4; nt++)
                mma_tf32(acc[mt][nt], a[mt], b[nt]);
    }

    // ---- epilogue ----
    const int g = lane >> 2, tg = lane & 3;
#pragma unroll
    for (int mt = 0; mt < 4; mt++) {
        int r0 = m0 + wm * 64 + mt * 16 + g;
        int r1 = r0 + 8;
        float d2_0 = 0.f, d2_1 = 0.f;
        if (layer_mode) {
            if (r0 < M) { float dv = g_dinv[r0]; d2_0 = dv * dv; }
            if (r1 < M) { float dv = g_dinv[r1]; d2_1 = dv * dv; }
        }
#pragma unroll
        for (int nt = 0; nt < 4; nt++) {
            int col = wn * 32 + nt * 8 + tg * 2;
            float2 bb = *(const float2*)&bias[col];
            float2 v0 = make_float2(acc[mt][nt][0], acc[mt][nt][1]);
            float2 v1 = make_float2(acc[mt][nt][2], acc[mt][nt][3]);
            if (layer_mode) {
                if (r0 < M) {
                    *(float2*)&y_out[(size_t)r0 * HDIM + col] = v0;
                    float2 o; o.x = v0.x * d2_0 + bb.x; o.y = v0.y * d2_0 + bb.y;
                    *(float2*)&x_out[(size_t)r0 * HDIM + col] = o;
                }
                if (r1 < M) {
                    *(float2*)&y_out[(size_t)r1 * HDIM + col] = v1;
                    float2 o; o.x = v1.x * d2_1 + bb.x; o.y = v1.y * d2_1 + bb.y;
                    *(float2*)&x_out[(size_t)r1 * HDIM + col] = o;
                }
            } else {
                if (r0 < M) {
                    float2 o; o.x = v0.x + bb.x; o.y = v0.y + bb.y;
                    *(float2*)&x_out[(size_t)r0 * HDIM + col] = o;
                }
                if (r1 < M) {
                    float2 o; o.x = v1.x + bb.x; o.y = v1.y + bb.y;
                    *(float2*)&x_out[(size_t)r1 * HDIM + col] = o;
                }
            }
        }
    }
}

// ---------------------------------------------------------------------------
// Edge scatter: one warp per edge, lane = one float4 of the 128-wide row
// ---------------------------------------------------------------------------
__global__ __launch_bounds__(256) void k_scatter() {
    int gtid = blockIdx.x * blockDim.x + threadIdx.x;
    int wid = gtid >> 5;
    int lane = gtid & 31;
    if (wid >= NE) return;
    int s = g_src[wid];
    int d = g_dst[wid];
    float norm = g_dinv[s] * g_dinv[d];
    float4 v = *(const float4*)&g_y[(size_t)s * HDIM + lane * 4];
    v.x *= norm; v.y *= norm; v.z *= norm; v.w *= norm;
    float* p = &g_x[(size_t)d * HDIM + lane * 4];
    asm volatile("red.global.add.v4.f32 [%0], {%1,%2,%3,%4};"
                 :: "l"(p), "f"(v.x), "f"(v.y), "f"(v.z), "f"(v.w)
                 : "memory");
}

// ---------------------------------------------------------------------------
// Output GEMM: out[NN,16] = relu(g_x) @ Wo + bo   (SIMT, small)
// ---------------------------------------------------------------------------
__global__ __launch_bounds__(256) void k_out(
    const float* __restrict__ Wo, const float* __restrict__ bo,
    float* __restrict__ out)
{
    __shared__ float sX[64][HDIM];
    __shared__ float sW[HDIM][ODIM];
    const int tid = threadIdx.x;
    const int m0 = blockIdx.x * 64;

#pragma unroll
    for (int it = 0; it < 8; it++) {
        int idx = tid + it * 256;
        int r = idx >> 5;
        int c4 = (idx & 31) * 4;
        int gm = m0 + r;
        float4 v = make_float4(0.f, 0.f, 0.f, 0.f);
        if (gm < NN) v = *(const float4*)&g_x[(size_t)gm * HDIM + c4];
        v.x = fmaxf(v.x, 0.f); v.y = fmaxf(v.y, 0.f);
        v.z = fmaxf(v.z, 0.f); v.w = fmaxf(v.w, 0.f);
        *(float4*)&sX[r][c4] = v;
    }
#pragma unroll
    for (int it = 0; it < 8; it++) {
        int idx = tid + it * 256;
        ((float*)sW)[idx] = Wo[idx];
    }
    __syncthreads();

    const int col = tid & 15;
    const int r0 = (tid >> 4) * 4;
    float acc[4] = {0.f, 0.f, 0.f, 0.f};
#pragma unroll 4
    for (int k = 0; k < HDIM; k++) {
        float w = sW[k][col];
        acc[0] += sX[r0 + 0][k] * w;
        acc[1] += sX[r0 + 1][k] * w;
        acc[2] += sX[r0 + 2][k] * w;
        acc[3] += sX[r0 + 3][k] * w;
    }
    float bb = bo[col];
#pragma unroll
    for (int i = 0; i < 4; i++) {
        int gm = m0 + r0 + i;
        if (gm < NN) out[(size_t)gm * ODIM + col] = acc[i] + bb;
    }
}

// ---------------------------------------------------------------------------
extern "C" void kernel_launch(void* const* d_in, const int* in_sizes, int n_in,
                              void* d_out, int out_size) {
    const float* user = (const float*)d_in[0];
    const float* prod = (const float*)d_in[1];
    const void*  edges = d_in[2];
    const float* Wu = (const float*)d_in[3];
    const float* bu = (const float*)d_in[4];
    const float* Wp = (const float*)d_in[5];
    const float* bp = (const float*)d_in[6];
    const float* W1 = (const float*)d_in[7];
    const float* b1 = (const float*)d_in[8];
    const float* W2 = (const float*)d_in[9];
    const float* b2 = (const float*)d_in[10];
    const float* W3 = (const float*)d_in[11];
    const float* b3 = (const float*)d_in[12];
    const float* Wo = (const float*)d_in[13];
    const float* bo = (const float*)d_in[14];
    float* out = (float*)d_out;

    float *px = nullptr, *py = nullptr;
    cudaGetSymbolAddress((void**)&px, g_x);
    cudaGetSymbolAddress((void**)&py, g_y);

    cudaFuncSetAttribute(k_gemm_mma, cudaFuncAttributeMaxDynamicSharedMemorySize, 131072);

    k_detect<<<1, 32>>>(edges);
    k_convert<<<(NE + 255) / 256, 256>>>(edges);
    k_deg_init<<<(NN + 255) / 256, 256>>>();
    k_deg_count<<<(NE + 255) / 256, 256>>>();
    k_dinv<<<(NN + 255) / 256, 256>>>();

    // Input transforms -> g_x (tensor core tf32; K padded to /8)
    {
        int k8 = (64 + 7) / 8;     // 8
        k_gemm_mma<<<(N_USERS + 127) / 128, 256, k8 * 8192>>>(
            user, 64, N_USERS, 64, Wu, bu, nullptr, px, 0, 0);
    }
    {
        int k8 = (100 + 7) / 8;    // 13
        k_gemm_mma<<<(N_PRODS + 127) / 128, 256, k8 * 8192>>>(
            prod, 100, N_PRODS, 100, Wp, bp, nullptr,
            px + (size_t)N_USERS * HDIM, 0, 0);
    }

    const float* Ws[3] = {W1, W2, W3};
    const float* bs[3] = {b1, b2, b3};
    for (int l = 0; l < 3; l++) {
        // y = (relu?)(x) @ W ; x = y*dinv^2 + b fused in epilogue
        k_gemm_mma<<<(NN + 127) / 128, 256, 16 * 8192>>>(
            px, 128, NN, 128, Ws[l], bs[l], py, px, l > 0 ? 1 : 0, 1);
        // x[dst] += y[src]*norm over edges
        k_scatter<<<(NE * 32 + 255) / 256, 256>>>();
    }
    k_out<<<(NN + 63) / 64, 256>>>(Wo, bo, out);
}

// round 4
// speedup vs baseline: 1.7753x; 1.7743x over previous
#include <cuda_runtime.h>
#include <cstdint>
#include <cstddef>

#define N_USERS 50000
#define N_PRODS 50000
#define NN      100000
#define NE      600000
#define HDIM    128
#define ODIM    16
#define NBLK1   98        // ceil(NN/1024)

// Scratch (__device__ globals: allocation-free rule)
__device__ float g_x[(size_t)NN * HDIM];
__device__ float g_y[(size_t)NN * HDIM];
__device__ float g_dinv[NN];
__device__ int   g_deg[NN];
__device__ int   g_rowstart[NN + 1];
__device__ int   g_cursor[NN];
__device__ int   g_esrc[NE];
__device__ int   g_blksum[NBLK1];
__device__ int   g_is64;

// ---------------------------------------------------------------------------
// Edge dtype detect + CSR build
// ---------------------------------------------------------------------------
__global__ void k_detect(const void* __restrict__ edges) {
    if (threadIdx.x == 0 && blockIdx.x == 0) {
        const unsigned int* w = (const unsigned int*)edges;
        int is64 = 1;
        for (int i = 0; i < 64; i++)
            if (w[2 * i + 1] != 0u) { is64 = 0; break; }
        g_is64 = is64;
    }
}
__global__ void k_zero() {
    int i = blockIdx.x * blockDim.x + threadIdx.x;
    if (i < NN) g_deg[i] = 0;
}
__device__ __forceinline__ void load_edge(const void* edges, int i, int& s, int& d) {
    if (g_is64) {
        const long long* e = (const long long*)edges;
        s = (int)e[i]; d = (int)e[NE + i];
    } else {
        const int* e = (const int*)edges;
        s = e[i]; d = e[NE + i];
    }
}
__global__ void k_hist(const void* __restrict__ edges) {
    int i = blockIdx.x * blockDim.x + threadIdx.x;
    if (i >= NE) return;
    int s, d; load_edge(edges, i, s, d);
    atomicAdd(&g_deg[d], 1);
}
__global__ __launch_bounds__(256) void k_scan1() {
    __shared__ int wsum[8], wbase[8];
    int b = blockIdx.x, tid = threadIdx.x;
    int base = b * 1024 + tid * 4;
    int v0 = 0, v1 = 0, v2 = 0, v3 = 0;
    if (base + 3 < NN) {
        int4 t = *(const int4*)&g_deg[base];
        v0 = t.x; v1 = t.y; v2 = t.z; v3 = t.w;
    } else {
        if (base + 0 < NN) v0 = g_deg[base + 0];
        if (base + 1 < NN) v1 = g_deg[base + 1];
        if (base + 2 < NN) v2 = g_deg[base + 2];
        if (base + 3 < NN) v3 = g_deg[base + 3];
    }
    int s = v0 + v1 + v2 + v3;
    int lane = tid & 31, w = tid >> 5;
    int x = s;
#pragma unroll
    for (int off = 1; off < 32; off <<= 1) {
        int t = __shfl_up_sync(0xffffffffu, x, off);
        if (lane >= off) x += t;
    }
    if (lane == 31) wsum[w] = x;
    __syncthreads();
    if (tid == 0) {
        int run = 0;
#pragma unroll
        for (int i = 0; i < 8; i++) { wbase[i] = run; run += wsum[i]; }
        g_blksum[b] = run;
    }
    __syncthreads();
    int ex = wbase[w] + x - s;
    if (base + 0 < NN) g_rowstart[base + 0] = ex;
    if (base + 1 < NN) g_rowstart[base + 1] = ex + v0;
    if (base + 2 < NN) g_rowstart[base + 2] = ex + v0 + v1;
    if (base + 3 < NN) g_rowstart[base + 3] = ex + v0 + v1 + v2;
}
__global__ __launch_bounds__(128) void k_scan2() {
    __shared__ int sh[NBLK1];
    int tid = threadIdx.x;
    if (tid < NBLK1) sh[tid] = g_blksum[tid];
    __syncthreads();
    if (tid == 0) {
        int run = 0;
        for (int i = 0; i < NBLK1; i++) { int t = sh[i]; sh[i] = run; run += t; }
    }
    __syncthreads();
    if (tid < NBLK1) g_blksum[tid] = sh[tid];
}
__global__ void k_scan3() {
    int i = blockIdx.x * blockDim.x + threadIdx.x;
    if (i >= NN) return;
    int rs = g_rowstart[i] + g_blksum[i >> 10];
    g_rowstart[i] = rs;
    g_cursor[i] = rs;
    g_dinv[i] = rsqrtf((float)g_deg[i] + 1.0f);
    if (i == 0) g_rowstart[NN] = NE;
}
__global__ void k_fill(const void* __restrict__ edges) {
    int i = blockIdx.x * blockDim.x + threadIdx.x;
    if (i >= NE) return;
    int s, d; load_edge(edges, i, s, d);
    int pos = atomicAdd(&g_cursor[d], 1);
    g_esrc[pos] = s;
}

// ---------------------------------------------------------------------------
// tf32 mma.sync GEMM, 512 threads, 128x128 CTA tile, K chunked by 64.
// Fragment-major SMEM (per-lane words contiguous) -> LDS.128/LDS.64 mainloop.
// m16n8k8 tf32 maps: A(r,c): lane=(r&7)*4+(c&3), reg=2*((c>>2)&1)+((r>>3)&1)
//                    B(k,n): lane=(n&7)*4+(k&3), reg=(k>>2)&1
//                    C: rows g|g+8 (g=lane>>2), cols 2*tg|2*tg+1 (tg=lane&3)
// mode=0: out = acc + bias   (input transform -> g_x)
// mode=1: out = acc          (layer -> g_y; bias/selfloop handled in gather)
// ---------------------------------------------------------------------------
__device__ __forceinline__ uint32_t f2tf32(float f) {
    uint32_t u;
    asm("cvt.rna.tf32.f32 %0, %1;" : "=r"(u) : "f"(f));
    return u;
}
__device__ __forceinline__ void mma_tf32(float* c, const uint32_t* a, const uint32_t* b) {
    asm volatile(
        "mma.sync.aligned.m16n8k8.row.col.f32.tf32.tf32.f32 "
        "{%0,%1,%2,%3}, {%4,%5,%6,%7}, {%8,%9}, {%0,%1,%2,%3};"
        : "+f"(c[0]), "+f"(c[1]), "+f"(c[2]), "+f"(c[3])
        : "r"(a[0]), "r"(a[1]), "r"(a[2]), "r"(a[3]), "r"(b[0]), "r"(b[1]));
}

__global__ __launch_bounds__(512) void k_gemm_mma(
    const float* __restrict__ A, int lda, int M, int Kdim,
    const float* __restrict__ W, const float* __restrict__ bias,
    float* __restrict__ out, int relu_in, int mode)
{
    extern __shared__ uint32_t smf[];
    uint32_t* Af = smf;            // 8 k8 x 8 mtiles x 128 words = 32KB
    uint32_t* Bf = smf + 8192;     // 8 k8 x 16 ntiles x 64 words = 32KB

    const int tid = threadIdx.x;
    const int wid = tid >> 5;
    const int lane = tid & 31;
    const int m0 = blockIdx.x * 128;
    const int wm = wid & 3;        // m-block of 32
    const int wn = wid >> 2;       // n-block of 32

    float acc[2][4][4];
#pragma unroll
    for (int mt = 0; mt < 2; mt++)
#pragma unroll
        for (int nt = 0; nt < 4; nt++)
#pragma unroll
            for (int j = 0; j < 4; j++) acc[mt][nt][j] = 0.f;

    const int nch = (Kdim + 63) >> 6;
    for (int ch = 0; ch < nch; ch++) {
        const int kbase = ch * 64;
        if (ch) __syncthreads();
        // ---- stage A chunk: 128 rows x 64 cols ----
#pragma unroll
        for (int it = 0; it < 4; it++) {
            int idx4 = tid + it * 512;           // 0..2047
            int r = idx4 >> 4;                   // 0..127
            int c4 = (idx4 & 15) << 2;           // 0..60
            int gm = m0 + r;
            int gc = kbase + c4;
            float4 v = make_float4(0.f, 0.f, 0.f, 0.f);
            if (gm < M && gc < Kdim) {
                if (gc + 3 < Kdim) {
                    v = *(const float4*)&A[(size_t)gm * lda + gc];
                } else {
                    const float* p = &A[(size_t)gm * lda];
                    v.x = p[gc];
                    if (gc + 1 < Kdim) v.y = p[gc + 1];
                    if (gc + 2 < Kdim) v.z = p[gc + 2];
                }
            }
            if (relu_in) {
                v.x = fmaxf(v.x, 0.f); v.y = fmaxf(v.y, 0.f);
                v.z = fmaxf(v.z, 0.f); v.w = fmaxf(v.w, 0.f);
            }
            uint32_t base = (uint32_t)(((c4 >> 3) * 8 + (r >> 4)) * 128
                          + (r & 7) * 16 + ((c4 >> 2) & 1) * 2 + ((r >> 3) & 1));
            Af[base + 0] = f2tf32(v.x);
            Af[base + 4] = f2tf32(v.y);
            Af[base + 8] = f2tf32(v.z);
            Af[base + 12] = f2tf32(v.w);
        }
        // ---- stage B chunk: 64 k x 128 n ----
#pragma unroll
        for (int it = 0; it < 16; it++) {
            int idx = tid + it * 512;            // 0..8191
            int k = idx >> 7, n = idx & 127;
            int gk = kbase + k;
            float v = (gk < Kdim) ? W[(size_t)gk * HDIM + n] : 0.f;
            uint32_t off = (uint32_t)(((k >> 3) * 16 + (n >> 3)) * 64
                         + ((n & 7) * 4 + (k & 3)) * 2 + ((k >> 2) & 1));
            Bf[off] = f2tf32(v);
        }
        __syncthreads();

        const uint32_t* Aw = Af + (wm * 2) * 128 + lane * 4;
        const uint32_t* Bw = Bf + (wn * 4) * 64 + lane * 2;
#pragma unroll
        for (int k8 = 0; k8 < 8; k8++) {
            uint32_t a[2][4], b[4][2];
#pragma unroll
            for (int mt = 0; mt < 2; mt++) {
                uint4 t = *(const uint4*)(Aw + (k8 * 8 + mt) * 128);
                a[mt][0] = t.x; a[mt][1] = t.y; a[mt][2] = t.z; a[mt][3] = t.w;
            }
#pragma unroll
            for (int nt = 0; nt < 4; nt++) {
                uint2 t = *(const uint2*)(Bw + (k8 * 16 + nt) * 64);
                b[nt][0] = t.x; b[nt][1] = t.y;
            }
#pragma unroll
            for (int mt = 0; mt < 2; mt++)
#pragma unroll
                for (int nt = 0; nt < 4; nt++)
                    mma_tf32(acc[mt][nt], a[mt], b[nt]);
        }
    }

    // ---- epilogue ----
    const int g = lane >> 2, tg = lane & 3;
#pragma unroll
    for (int mt = 0; mt < 2; mt++) {
        int r0 = m0 + wm * 32 + mt * 16 + g;
        int r1 = r0 + 8;
#pragma unroll
        for (int nt = 0; nt < 4; nt++) {
            int col = wn * 32 + nt * 8 + tg * 2;
            float2 v0 = make_float2(acc[mt][nt][0], acc[mt][nt][1]);
            float2 v1 = make_float2(acc[mt][nt][2], acc[mt][nt][3]);
            if (mode == 0) {
                float2 bb = *(const float2*)&bias[col];
                v0.x += bb.x; v0.y += bb.y;
                v1.x += bb.x; v1.y += bb.y;
            }
            if (r0 < M) *(float2*)&out[(size_t)r0 * HDIM + col] = v0;
            if (r1 < M) *(float2*)&out[(size_t)r1 * HDIM + col] = v1;
        }
    }
}

// ---------------------------------------------------------------------------
// CSR gather: warp per node. acc = y[d]*dinv[d] + sum y[s]*dinv[s];
// x[d] = acc*dinv[d] + bias.
// ---------------------------------------------------------------------------
__global__ __launch_bounds__(256) void k_gather(const float* __restrict__ bias) {
    int gt = blockIdx.x * blockDim.x + threadIdx.x;
    int node = gt >> 5;
    int lane = gt & 31;
    if (node >= NN) return;

    float dd = g_dinv[node];
    float4 acc = *(const float4*)&g_y[(size_t)node * HDIM + lane * 4];
    acc.x *= dd; acc.y *= dd; acc.z *= dd; acc.w *= dd;

    int e = g_rowstart[node];
    const int end = g_rowstart[node + 1];
    // 4-wide software pipeline: independent loads per iteration
    for (; e + 4 <= end; e += 4) {
        int s0 = g_esrc[e], s1 = g_esrc[e + 1], s2 = g_esrc[e + 2], s3 = g_esrc[e + 3];
        float n0 = g_dinv[s0], n1 = g_dinv[s1], n2 = g_dinv[s2], n3 = g_dinv[s3];
        float4 a = *(const float4*)&g_y[(size_t)s0 * HDIM + lane * 4];
        float4 b = *(const float4*)&g_y[(size_t)s1 * HDIM + lane * 4];
        float4 c = *(const float4*)&g_y[(size_t)s2 * HDIM + lane * 4];
        float4 d = *(const float4*)&g_y[(size_t)s3 * HDIM + lane * 4];
        acc.x += a.x * n0 + b.x * n1 + c.x * n2 + d.x * n3;
        acc.y += a.y * n0 + b.y * n1 + c.y * n2 + d.y * n3;
        acc.z += a.z * n0 + b.z * n1 + c.z * n2 + d.z * n3;
        acc.w += a.w * n0 + b.w * n1 + c.w * n2 + d.w * n3;
    }
    for (; e < end; e++) {
        int s = g_esrc[e];
        float ns = g_dinv[s];
        float4 a = *(const float4*)&g_y[(size_t)s * HDIM + lane * 4];
        acc.x += a.x * ns; acc.y += a.y * ns; acc.z += a.z * ns; acc.w += a.w * ns;
    }
    float4 bb = *(const float4*)&bias[lane * 4];
    float4 o;
    o.x = acc.x * dd + bb.x; o.y = acc.y * dd + bb.y;
    o.z = acc.z * dd + bb.z; o.w = acc.w * dd + bb.w;
    *(float4*)&g_x[(size_t)node * HDIM + lane * 4] = o;
}

// ---------------------------------------------------------------------------
// Output GEMM: out[NN,16] = relu(g_x) @ Wo + bo
// ---------------------------------------------------------------------------
__global__ __launch_bounds__(256) void k_out(
    const float* __restrict__ Wo, const float* __restrict__ bo,
    float* __restrict__ out)
{
    __shared__ float sX[64][HDIM];
    __shared__ float sW[HDIM][ODIM];
    const int tid = threadIdx.x;
    const int m0 = blockIdx.x * 64;

#pragma unroll
    for (int it = 0; it < 8; it++) {
        int idx = tid + it * 256;
        int r = idx >> 5;
        int c4 = (idx & 31) * 4;
        int gm = m0 + r;
        float4 v = make_float4(0.f, 0.f, 0.f, 0.f);
        if (gm < NN) v = *(const float4*)&g_x[(size_t)gm * HDIM + c4];
        v.x = fmaxf(v.x, 0.f); v.y = fmaxf(v.y, 0.f);
        v.z = fmaxf(v.z, 0.f); v.w = fmaxf(v.w, 0.f);
        *(float4*)&sX[r][c4] = v;
    }
#pragma unroll
    for (int it = 0; it < 8; it++) {
        int idx = tid + it * 256;
        ((float*)sW)[idx] = Wo[idx];
    }
    __syncthreads();

    const int col = tid & 15;
    const int r0 = (tid >> 4) * 4;
    float acc[4] = {0.f, 0.f, 0.f, 0.f};
#pragma unroll 4
    for (int k = 0; k < HDIM; k++) {
        float w = sW[k][col];
        acc[0] += sX[r0 + 0][k] * w;
        acc[1] += sX[r0 + 1][k] * w;
        acc[2] += sX[r0 + 2][k] * w;
        acc[3] += sX[r0 + 3][k] * w;
    }
    float bb = bo[col];
#pragma unroll
    for (int i = 0; i < 4; i++) {
        int gm = m0 + r0 + i;
        if (gm < NN) out[(size_t)gm * ODIM + col] = acc[i] + bb;
    }
}

// ---------------------------------------------------------------------------
extern "C" void kernel_launch(void* const* d_in, const int* in_sizes, int n_in,
                              void* d_out, int out_size) {
    const float* user = (const float*)d_in[0];
    const float* prod = (const float*)d_in[1];
    const void*  edges = d_in[2];
    const float* Wu = (const float*)d_in[3];
    const float* bu = (const float*)d_in[4];
    const float* Wp = (const float*)d_in[5];
    const float* bp = (const float*)d_in[6];
    const float* W1 = (const float*)d_in[7];
    const float* b1 = (const float*)d_in[8];
    const float* W2 = (const float*)d_in[9];
    const float* b2 = (const float*)d_in[10];
    const float* W3 = (const float*)d_in[11];
    const float* b3 = (const float*)d_in[12];
    const float* Wo = (const float*)d_in[13];
    const float* bo = (const float*)d_in[14];
    float* out = (float*)d_out;

    float *px = nullptr, *py = nullptr;
    cudaGetSymbolAddress((void**)&px, g_x);
    cudaGetSymbolAddress((void**)&py, g_y);

    cudaFuncSetAttribute(k_gemm_mma, cudaFuncAttributeMaxDynamicSharedMemorySize, 65536);

    // CSR build
    k_detect<<<1, 32>>>(edges);
    k_zero<<<(NN + 255) / 256, 256>>>();
    k_hist<<<(NE + 255) / 256, 256>>>(edges);
    k_scan1<<<NBLK1, 256>>>();
    k_scan2<<<1, 128>>>();
    k_scan3<<<(NN + 255) / 256, 256>>>();
    k_fill<<<(NE + 255) / 256, 256>>>(edges);

    // Input transforms -> g_x
    k_gemm_mma<<<(N_USERS + 127) / 128, 512, 65536>>>(
        user, 64, N_USERS, 64, Wu, bu, px, 0, 0);
    k_gemm_mma<<<(N_PRODS + 127) / 128, 512, 65536>>>(
        prod, 100, N_PRODS, 100, Wp, bp, px + (size_t)N_USERS * HDIM, 0, 0);

    const float* Ws[3] = {W1, W2, W3};
    const float* bs[3] = {b1, b2, b3};
    for (int l = 0; l < 3; l++) {
        // y = (relu?)(x) @ W
        k_gemm_mma<<<(NN + 127) / 128, 512, 65536>>>(
            px, 128, NN, 128, Ws[l], nullptr, py, l > 0 ? 1 : 0, 1);
        // x = gather(y) + bias (self-loop + sym-norm fused)
        k_gather<<<(NN * 32 + 255) / 256, 256>>>(bs[l]);
    }
    k_out<<<(NN + 63) / 64, 256>>>(Wo, bo, out);
}